// round 1
// baseline (speedup 1.0000x reference)
#include <cuda_runtime.h>

// Problem constants (fixed for FeedBack_953482740249)
#define B_   1024
#define T_   128
#define F_   128
#define U_   512
#define S_   96
#define NG   2048      // 4*U
#define KWARM (F_ + U_) // 640

// ---------------- device scratch (static: no allocations allowed) ----------
__device__ __align__(128) float g_h[2][B_ * U_];   // ping-pong hidden state
__device__ __align__(128) float g_c[B_ * U_];      // cell state (in-place)
__device__ __align__(128) float g_Wwarm[KWARM * NG]; // [ [Wk;Wr] ] gate-permuted
__device__ __align__(128) float g_Wdec[U_ * NG];     // Wr + Wd@Wk, gate-permuted
__device__ __align__(128) float g_bwarm[NG];
__device__ __align__(128) float g_bdec[NG];

// Gate-interleaved permutation: permuted col j -> original col (j&3)*U + (j>>2)
// so each unit's 4 gates [i,f,g,o] are adjacent.

// ---------------- f32x2 helpers --------------------------------------------
__device__ __forceinline__ unsigned long long pack2(float x, float y) {
    unsigned long long r;
    asm("mov.b64 %0, {%1, %2};" : "=l"(r)
        : "r"(__float_as_uint(x)), "r"(__float_as_uint(y)));
    return r;
}
__device__ __forceinline__ void ffma2(unsigned long long& d,
                                      unsigned long long a,
                                      unsigned long long b) {
    asm("fma.rn.f32x2 %0, %1, %2, %0;" : "+l"(d) : "l"(a), "l"(b));
}
__device__ __forceinline__ float2 unpack2(unsigned long long v) {
    unsigned int lo, hi;
    asm("mov.b64 {%0, %1}, %2;" : "=r"(lo), "=r"(hi) : "l"(v));
    float2 r; r.x = __uint_as_float(lo); r.y = __uint_as_float(hi);
    return r;
}

// ---------------- setup kernels --------------------------------------------
__global__ void k_zero_hc() {
    int i = blockIdx.x * blockDim.x + threadIdx.x;
    if (i < B_ * U_) { g_h[0][i] = 0.f; g_c[i] = 0.f; }
}

// Build permuted warmup weight [Wk; Wr] (rows 0..F-1 from Wk, F..F+U-1 from Wr)
__global__ void k_perm_warm(const float* __restrict__ Wk,
                            const float* __restrict__ Wr,
                            const float* __restrict__ b) {
    int i = blockIdx.x * blockDim.x + threadIdx.x; // 0 .. KWARM*NG-1
    int k = i >> 11;           // row
    int j = i & (NG - 1);      // permuted col
    int col = (j & 3) * U_ + (j >> 2);
    float v = (k < F_) ? Wk[k * NG + col] : Wr[(k - F_) * NG + col];
    g_Wwarm[i] = v;
    if (k == 0) g_bwarm[j] = b[col];
}

// g_Wdec[k][j] = Wr[k][col] + sum_f Wd[k][f] * Wk[f][col]   (gate-permuted)
// grid (U_, 2), block 256. Each thread: 4 consecutive units, one gate.
__global__ void k_dec_weight(const float* __restrict__ Wk,
                             const float* __restrict__ Wr,
                             const float* __restrict__ Wd) {
    int k = blockIdx.x;
    int grp = blockIdx.y * 256 + threadIdx.x;  // 0..511
    int gate = grp >> 7;          // 0..3
    int u0 = (grp & 127) * 4;     // 0,4,...,508
    __shared__ float wd[F_];
    if (threadIdx.x < F_) wd[threadIdx.x] = Wd[k * F_ + threadIdx.x];
    __syncthreads();
    int col0 = gate * U_ + u0;
    float4 acc = make_float4(0.f, 0.f, 0.f, 0.f);
    for (int f = 0; f < F_; ++f) {
        float4 wk = *(const float4*)&Wk[(size_t)f * NG + col0];
        float d = wd[f];
        acc.x = fmaf(d, wk.x, acc.x);
        acc.y = fmaf(d, wk.y, acc.y);
        acc.z = fmaf(d, wk.z, acc.z);
        acc.w = fmaf(d, wk.w, acc.w);
    }
    const float* wr = &Wr[(size_t)k * NG + col0];
    float* dst = &g_Wdec[(size_t)k * NG];
    dst[(u0 + 0) * 4 + gate] = acc.x + wr[0];
    dst[(u0 + 1) * 4 + gate] = acc.y + wr[1];
    dst[(u0 + 2) * 4 + gate] = acc.z + wr[2];
    dst[(u0 + 3) * 4 + gate] = acc.w + wr[3];
}

// g_bdec[j] = b[col] + sum_f bd[f]*Wk[f][col]
__global__ void k_bias_dec(const float* __restrict__ Wk,
                           const float* __restrict__ b,
                           const float* __restrict__ bd) {
    int j = blockIdx.x * blockDim.x + threadIdx.x; // 0..2047
    int col = (j & 3) * U_ + (j >> 2);
    float acc = b[col];
    for (int f = 0; f < F_; ++f) acc = fmaf(bd[f], Wk[(size_t)f * NG + col], acc);
    g_bdec[j] = acc;
}

// ---------------- per-step fused GEMM + LSTM cell --------------------------
#define BM 128
#define BN 128
#define BK 16

// Blocks [0, nCell): cell GEMM  z = [x|h] @ Wg + bg, fused gate update -> h,c
// Blocks [nCell, nCell+8): pred GEMM  out = h @ Wd + bd (reads h BEFORE update)
__global__ __launch_bounds__(256)
void k_step(const float* __restrict__ x,   // inputs + t*F (warmup) / unused
            int useDec,                    // 0 = warmup, 1 = decode
            int hrIdx,                     // read buffer index for g_h
            const float* __restrict__ Wd,
            const float* __restrict__ bd,
            float* __restrict__ outp,      // d_out + s*F (pred blocks) / unused
            int nCell)
{
    __shared__ __align__(16) float As[2][BK][BM];
    __shared__ __align__(16) float Bs[2][BK][BN];

    const float* hR = g_h[hrIdx];
    float*       hW = g_h[hrIdx ^ 1];

    const int tid = threadIdx.x;
    const int tx  = tid & 15;
    const int ty  = tid >> 4;

    const bool isPred = ((int)blockIdx.x >= nCell);
    int bm0, bn0, ldW, K, kx;
    const float* W;
    if (!isPred) {
        bm0 = (blockIdx.x >> 4) * BM;
        bn0 = (blockIdx.x & 15) * BN;
        W   = useDec ? g_Wdec : g_Wwarm;
        ldW = NG;
        K   = useDec ? U_ : KWARM;
        kx  = useDec ? 0 : F_;
    } else {
        bm0 = (blockIdx.x - nCell) * BM;
        bn0 = 0;
        W   = Wd;
        ldW = F_;
        K   = U_;
        kx  = 0;
    }

    unsigned long long acc[8][4];
#pragma unroll
    for (int m = 0; m < 8; ++m)
#pragma unroll
        for (int n = 0; n < 4; ++n) acc[m][n] = 0ull;

    float4 aR[2], bR[2];

    auto loadG = [&](int k0) {
#pragma unroll
        for (int p = 0; p < 2; ++p) {
            int idx = tid + p * 256;
            // A: m = idx&127 (row within tile), c4 = idx>>7 (float4 k-chunk)
            int m  = idx & 127;
            int c4 = idx >> 7;
            int gk = k0 + c4 * 4;
            const float* src;
            if (gk < kx) src = x  + (size_t)(bm0 + m) * (T_ * F_) + gk;
            else         src = hR + (size_t)(bm0 + m) * U_ + (gk - kx);
            aR[p] = *(const float4*)src;
            // B: r = idx>>5 (k row), c = idx&31 (float4 col chunk) -> coalesced
            int r = idx >> 5;
            int c = idx & 31;
            bR[p] = *(const float4*)&W[(size_t)(k0 + r) * ldW + bn0 + c * 4];
        }
    };
    auto storeS = [&](int buf) {
#pragma unroll
        for (int p = 0; p < 2; ++p) {
            int idx = tid + p * 256;
            int m  = idx & 127;
            int c4 = idx >> 7;
            As[buf][c4 * 4 + 0][m] = aR[p].x;
            As[buf][c4 * 4 + 1][m] = aR[p].y;
            As[buf][c4 * 4 + 2][m] = aR[p].z;
            As[buf][c4 * 4 + 3][m] = aR[p].w;
            int r = idx >> 5;
            int c = idx & 31;
            *(float4*)&Bs[buf][r][c * 4] = bR[p];
        }
    };

    const int nt = K / BK;
    loadG(0);
    storeS(0);
    __syncthreads();

    for (int t = 0; t < nt; ++t) {
        if (t + 1 < nt) loadG((t + 1) * BK);
        const int buf = t & 1;
#pragma unroll
        for (int kk = 0; kk < BK; ++kk) {
            float4 a0 = *(const float4*)&As[buf][kk][ty * 8];
            float4 a1 = *(const float4*)&As[buf][kk][ty * 8 + 4];
            const ulonglong2* bp = (const ulonglong2*)&Bs[buf][kk][tx * 8];
            ulonglong2 q0 = bp[0];
            ulonglong2 q1 = bp[1];
            unsigned long long bb[4] = {q0.x, q0.y, q1.x, q1.y};
            float am[8] = {a0.x, a0.y, a0.z, a0.w, a1.x, a1.y, a1.z, a1.w};
#pragma unroll
            for (int m = 0; m < 8; ++m) {
                unsigned long long a2 = pack2(am[m], am[m]);
#pragma unroll
                for (int n = 0; n < 4; ++n) ffma2(acc[m][n], a2, bb[n]);
            }
        }
        if (t + 1 < nt) storeS((t + 1) & 1);
        __syncthreads();
    }

    if (!isPred) {
        const float* bg = useDec ? g_bdec : g_bwarm;
#pragma unroll
        for (int m = 0; m < 8; ++m) {
            int bm = bm0 + ty * 8 + m;
#pragma unroll
            for (int uo = 0; uo < 2; ++uo) {
                float2 z01 = unpack2(acc[m][2 * uo]);
                float2 z23 = unpack2(acc[m][2 * uo + 1]);
                int jl = tx * 8 + uo * 4;
                float zi = z01.x + bg[bn0 + jl + 0];
                float zf = z01.y + bg[bn0 + jl + 1];
                float zg = z23.x + bg[bn0 + jl + 2];
                float zo = z23.y + bg[bn0 + jl + 3];
                float ig = 1.f / (1.f + expf(-zi));
                float fg = 1.f / (1.f + expf(-zf));
                float gg = tanhf(zg);
                float og = 1.f / (1.f + expf(-zo));
                int u = (bn0 >> 2) + tx * 2 + uo;
                size_t ci = (size_t)bm * U_ + u;
                float cn = fmaf(fg, g_c[ci], ig * gg);
                g_c[ci] = cn;
                hW[ci] = og * tanhf(cn);
            }
        }
    } else {
#pragma unroll
        for (int m = 0; m < 8; ++m) {
            int bm = bm0 + ty * 8 + m;
#pragma unroll
            for (int n = 0; n < 4; ++n) {
                float2 v = unpack2(acc[m][n]);
                int f0 = tx * 8 + 2 * n;
                outp[(size_t)bm * (S_ * F_) + f0]     = v.x + bd[f0];
                outp[(size_t)bm * (S_ * F_) + f0 + 1] = v.y + bd[f0 + 1];
            }
        }
    }
}

// ---------------- host launch ----------------------------------------------
extern "C" void kernel_launch(void* const* d_in, const int* in_sizes, int n_in,
                              void* d_out, int out_size) {
    const float* inputs = (const float*)d_in[0];
    const float* Wk     = (const float*)d_in[1];
    const float* Wr     = (const float*)d_in[2];
    const float* b      = (const float*)d_in[3];
    const float* Wd     = (const float*)d_in[4];
    const float* bd     = (const float*)d_in[5];
    float* out = (float*)d_out;

    // setup (recomputed every replay; deterministic)
    k_zero_hc<<<(B_ * U_ + 255) / 256, 256>>>();
    k_perm_warm<<<(KWARM * NG) / 256, 256>>>(Wk, Wr, b);
    k_dec_weight<<<dim3(U_, 2), 256>>>(Wk, Wr, Wd);
    k_bias_dec<<<NG / 256, 256>>>(Wk, b, bd);

    int q = 0;
    // warmup: 128 steps, cell only (128 blocks)
    for (int t = 0; t < T_; ++t, ++q) {
        k_step<<<128, 256>>>(inputs + (size_t)t * F_, /*useDec=*/0,
                             /*hrIdx=*/q & 1, Wd, bd, out, /*nCell=*/128);
    }
    // decode steps s = 1..S-1: cell (folded feedback) + pred of PREVIOUS h
    for (int s = 1; s < S_; ++s, ++q) {
        k_step<<<136, 256>>>(inputs, /*useDec=*/1, /*hrIdx=*/q & 1,
                             Wd, bd, out + (size_t)(s - 1) * F_, /*nCell=*/128);
    }
    // final pred: out[:, S-1, :] from last h (in g_h[(q)&1] after q steps)
    k_step<<<8, 256>>>(inputs, /*useDec=*/1, /*hrIdx=*/q & 1,
                       Wd, bd, out + (size_t)(S_ - 1) * F_, /*nCell=*/0);
}

// round 3
// speedup vs baseline: 1.5442x; 1.5442x over previous
#include <cuda_runtime.h>
#include <cuda_bf16.h>
#include <cstdint>

// Problem constants (fixed for FeedBack_953482740249)
#define B_   1024
#define T_   128
#define F_   128
#define U_   512
#define S_   96
#define NG   2048       // 4*U
#define KW   640        // warmup K per pass (F+U)
#define KD   512        // decode K per pass (U)
#define KPW  1920       // 3*KW  (A2=[Ah|Ah|Al], B2=[Bh|Bl|Bh])
#define KPD  1536       // 3*KD
#define NDEC 2176       // 2048 gate cols + 128 pred cols (Wd^T)

// ---------------- device state / precomputed weights -----------------------
__device__ __nv_bfloat16 g_xhi[B_ * T_ * F_];
__device__ __nv_bfloat16 g_xlo[B_ * T_ * F_];
__device__ __nv_bfloat16 g_W2w[(size_t)NG * KPW];    // [j][k'] K-major, permuted cols
__device__ __nv_bfloat16 g_W2d[(size_t)NDEC * KPD];  // rows 0..2047 folded cell, 2048.. Wd^T
__device__ float g_Wdec[(size_t)KD * NG];            // fp32 temp: Wr + Wd@Wk (native cols)
__device__ float g_bwarm[NG];                        // permuted
__device__ float g_bdec[NG];                         // permuted
__device__ __nv_bfloat16 g_hhi[2][B_ * U_];          // ping-pong hidden (bf16 hi)
__device__ __nv_bfloat16 g_hlo[2][B_ * U_];          // ping-pong hidden (bf16 lo)
__device__ float g_c[B_ * U_];

// Column permutation: permuted col j -> original col gate*U + unit, with
//   gate = ((j>>4)&1)*2 + (j&1),  unit = (j>>5)*8 + ((j>>1)&7)
// Within each 32-col slab: cols 2u,2u+1 = (i,f) of unit u; 16+2u,17+2u = (g,o).
__host__ __device__ __forceinline__ int perm_col(int j) {
    int gate = ((j >> 4) & 1) * 2 + (j & 1);
    int unit = (j >> 5) * 8 + ((j >> 1) & 7);
    return gate * U_ + unit;
}

// ---------------- PTX helpers ----------------------------------------------
__device__ __forceinline__ uint32_t smem_u32(const void* p) {
    uint32_t a;
    asm("{ .reg .u64 t; cvta.to.shared.u64 t, %1; cvt.u32.u64 %0, t; }"
        : "=r"(a) : "l"(p));
    return a;
}
__device__ __forceinline__ void cp16(uint32_t s, const void* g) {
    asm volatile("cp.async.cg.shared.global [%0], [%1], 16;" :: "r"(s), "l"(g));
}
__device__ __forceinline__ void ldx4(uint32_t* r, uint32_t addr) {
    asm volatile("ldmatrix.sync.aligned.m8n8.x4.shared.b16 {%0,%1,%2,%3}, [%4];"
        : "=r"(r[0]), "=r"(r[1]), "=r"(r[2]), "=r"(r[3]) : "r"(addr));
}
__device__ __forceinline__ void mma16816(float* d, const uint32_t* a, const uint32_t* b) {
    asm volatile(
        "mma.sync.aligned.m16n8k16.row.col.f32.bf16.bf16.f32 "
        "{%0,%1,%2,%3}, {%4,%5,%6,%7}, {%8,%9}, {%0,%1,%2,%3};"
        : "+f"(d[0]), "+f"(d[1]), "+f"(d[2]), "+f"(d[3])
        : "r"(a[0]), "r"(a[1]), "r"(a[2]), "r"(a[3]), "r"(b[0]), "r"(b[1]));
}

// ---------------- setup kernels --------------------------------------------
__global__ void k_split_x(const float* __restrict__ x) {
    int i = blockIdx.x * blockDim.x + threadIdx.x;
    float v = x[i];
    __nv_bfloat16 hi = __float2bfloat16(v);
    g_xhi[i] = hi;
    g_xlo[i] = __float2bfloat16(v - __bfloat162float(hi));
}

__global__ void k_init_state() {
    int i = blockIdx.x * blockDim.x + threadIdx.x;
    if (i < B_ * U_) {
        g_hhi[0][i] = __float2bfloat16(0.f);
        g_hlo[0][i] = __float2bfloat16(0.f);
        g_c[i] = 0.f;
    }
}

// Warm weights B2 = [Bh|Bl|Bh] over K'=1920, rows 0..F-1 = Wk, F.. = Wr.
__global__ void k_build_warm(const float* __restrict__ Wk,
                             const float* __restrict__ Wr,
                             const float* __restrict__ b) {
    size_t idx = (size_t)blockIdx.x * blockDim.x + threadIdx.x;
    if (idx >= (size_t)NG * KPW) return;
    int j  = (int)(idx / KPW);
    int kp = (int)(idx - (size_t)j * KPW);
    int pass = kp / KW;
    int kk = kp - pass * KW;
    int col = perm_col(j);
    float v = (kk < F_) ? Wk[(size_t)kk * NG + col]
                        : Wr[(size_t)(kk - F_) * NG + col];
    __nv_bfloat16 hi = __float2bfloat16(v);
    g_W2w[idx] = (pass == 1) ? __float2bfloat16(v - __bfloat162float(hi)) : hi;
    if (kp == 0) g_bwarm[j] = b[col];
}

// g_Wdec[k][col] = Wr[k][col] + sum_f Wd[k][f] * Wk[f][col]  (native cols)
__global__ void k_dec_weight(const float* __restrict__ Wk,
                             const float* __restrict__ Wr,
                             const float* __restrict__ Wd) {
    int k = blockIdx.x;
    int grp = blockIdx.y * 256 + threadIdx.x;  // 0..511
    int col0 = grp * 4;
    __shared__ float wd[F_];
    if (threadIdx.x < F_) wd[threadIdx.x] = Wd[k * F_ + threadIdx.x];
    __syncthreads();
    float4 acc = make_float4(0.f, 0.f, 0.f, 0.f);
    for (int f = 0; f < F_; ++f) {
        float4 wk = *(const float4*)&Wk[(size_t)f * NG + col0];
        float d = wd[f];
        acc.x = fmaf(d, wk.x, acc.x);
        acc.y = fmaf(d, wk.y, acc.y);
        acc.z = fmaf(d, wk.z, acc.z);
        acc.w = fmaf(d, wk.w, acc.w);
    }
    const float4 wr = *(const float4*)&Wr[(size_t)k * NG + col0];
    float4 o;
    o.x = acc.x + wr.x; o.y = acc.y + wr.y;
    o.z = acc.z + wr.z; o.w = acc.w + wr.w;
    *(float4*)&g_Wdec[(size_t)k * NG + col0] = o;
}

// Decode weights B2 over K'=1536; rows 2048..2175 are Wd^T (natural f order).
__global__ void k_build_dec(const float* __restrict__ Wd) {
    size_t idx = (size_t)blockIdx.x * blockDim.x + threadIdx.x;
    if (idx >= (size_t)NDEC * KPD) return;
    int j  = (int)(idx / KPD);
    int kp = (int)(idx - (size_t)j * KPD);
    int pass = kp >> 9;
    int kk = kp & 511;
    float v = (j < NG) ? g_Wdec[(size_t)kk * NG + perm_col(j)]
                       : Wd[(size_t)kk * F_ + (j - NG)];
    __nv_bfloat16 hi = __float2bfloat16(v);
    g_W2d[idx] = (pass == 1) ? __float2bfloat16(v - __bfloat162float(hi)) : hi;
}

// g_bdec[j] = b[col] + sum_f bd[f]*Wk[f][col]   (permuted)
__global__ void k_bias_dec(const float* __restrict__ Wk,
                           const float* __restrict__ b,
                           const float* __restrict__ bd) {
    int j = blockIdx.x * blockDim.x + threadIdx.x;
    int col = perm_col(j);
    float acc = b[col];
    for (int f = 0; f < F_; ++f) acc = fmaf(bd[f], Wk[(size_t)f * NG + col], acc);
    g_bdec[j] = acc;
}

// ---------------- per-step mma.sync GEMM + fused LSTM cell -----------------
// Block: 128(M) x 128(N), BK=32, 256 threads (8 warps: 2 m x 4 n).
// SMEM rows padded to 40 bf16 (80B) -> conflict-free ldmatrix.
#define ROWB 40          // bf16 elems per padded SMEM row
#define BUFB (128 * ROWB)

__global__ __launch_bounds__(256, 1)
void k_step(int warm, int xoff, int hrIdx, int nCellTiles, int bxOff,
            const float* __restrict__ bd, float* __restrict__ outp)
{
    __shared__ __align__(128) __nv_bfloat16 shA[2][BUFB];
    __shared__ __align__(128) __nv_bfloat16 shB[2][BUFB];

    const int tid  = threadIdx.x;
    const int lane = tid & 31;
    const int wid  = tid >> 5;
    const int wm   = wid & 1;     // 0..1 : 64 M-rows each
    const int wn   = wid >> 1;    // 0..3 : 32 N-cols each
    const int grp  = lane >> 2;
    const int tig  = lane & 3;

    const int bx  = blockIdx.x + bxOff;
    const int bm0 = blockIdx.y * 128;
    const int bn0 = bx * 128;
    const bool isPred = (bx >= nCellTiles);

    const int KP  = warm ? KPW : KPD;
    const int Kp1 = warm ? KW : KD;
    const int nc  = KP >> 5;
    const __nv_bfloat16* W   = warm ? g_W2w : g_W2d;
    const __nv_bfloat16* hhi = g_hhi[hrIdx];
    const __nv_bfloat16* hlo = g_hlo[hrIdx];
    const __nv_bfloat16* bb0 = W + (size_t)bn0 * KP;

    const uint32_t uA = smem_u32(shA);
    const uint32_t uB = smem_u32(shB);

    float acc[4][4][4];
#pragma unroll
    for (int mi = 0; mi < 4; ++mi)
#pragma unroll
        for (int ni = 0; ni < 4; ++ni)
#pragma unroll
            for (int r = 0; r < 4; ++r) acc[mi][ni][r] = 0.f;

    // --- async stage of one 32-wide K' chunk into buffer (c&1) ---
    auto stage = [&](int c) {
        const int buf = c & 1;
        const int k0  = c << 5;
        int pass = k0 / Kp1;
        int kk = k0 - pass * Kp1;
        const __nv_bfloat16* abase;
        int lda;
        const bool lo = (pass == 2);
        if (warm && kk < F_) {
            abase = (lo ? g_xlo : g_xhi) + (size_t)bm0 * (T_ * F_) + xoff + kk;
            lda = T_ * F_;
        } else {
            int kh = warm ? kk - F_ : kk;
            abase = (lo ? hlo : hhi) + (size_t)bm0 * U_ + kh;
            lda = U_;
        }
        const __nv_bfloat16* bb = bb0 + k0;
        const uint32_t sa = uA + buf * (BUFB * 2);
        const uint32_t sb = uB + buf * (BUFB * 2);
#pragma unroll
        for (int i = 0; i < 2; ++i) {
            int cc = tid + i * 256;        // 0..511 16B pieces
            int row = cc >> 2, kc = cc & 3;
            cp16(sa + row * 80 + kc * 16, abase + (size_t)row * lda + kc * 8);
            cp16(sb + row * 80 + kc * 16, bb + (size_t)row * KP + kc * 8);
        }
        asm volatile("cp.async.commit_group;" ::: "memory");
    };

    stage(0);
    for (int c = 0; c < nc; ++c) {
        __syncthreads();                    // done reading buf (c+1)&1
        if (c + 1 < nc) {
            stage(c + 1);
            asm volatile("cp.async.wait_group 1;" ::: "memory");
        } else {
            asm volatile("cp.async.wait_group 0;" ::: "memory");
        }
        __syncthreads();

        const uint32_t sa = uA + (c & 1) * (BUFB * 2);
        const uint32_t sb = uB + (c & 1) * (BUFB * 2);
#pragma unroll
        for (int ks = 0; ks < 2; ++ks) {
            uint32_t a[4][4], b[2][4];
            // A: lanes 0-7 rows 0-7 klo, 8-15 rows 8-15 klo, 16-23 rows 0-7 khi, 24-31 rows 8-15 khi
            uint32_t aaddr = sa + (uint32_t)(wm * 64 + (lane & 15)) * 80
                           + (uint32_t)(ks * 16 + (lane >> 4) * 8) * 2;
#pragma unroll
            for (int mi = 0; mi < 4; ++mi) ldx4(a[mi], aaddr + mi * 16 * 80);
            // B: lanes 0-7 n0..7 klo, 8-15 n0..7 khi, 16-23 n8..15 klo, 24-31 n8..15 khi
            uint32_t baddr = sb + (uint32_t)(wn * 32 + (lane & 7) + ((lane >> 4) & 1) * 8) * 80
                           + (uint32_t)(ks * 16 + ((lane >> 3) & 1) * 8) * 2;
#pragma unroll
            for (int g = 0; g < 2; ++g) ldx4(b[g], baddr + g * 16 * 80);
#pragma unroll
            for (int mi = 0; mi < 4; ++mi)
#pragma unroll
                for (int ni = 0; ni < 4; ++ni)
                    mma16816(acc[mi][ni], a[mi], &b[ni >> 1][(ni & 1) * 2]);
        }
    }

    // ---------------- fused epilogue ----------------
    if (!isPred) {
        const float* bg = warm ? g_bwarm : g_bdec;
        __nv_bfloat16* hwh = g_hhi[hrIdx ^ 1];
        __nv_bfloat16* hwl = g_hlo[hrIdx ^ 1];
        const int jsl = bn0 + wn * 32;
        const int ubl = (bn0 >> 2) + wn * 8;
#pragma unroll
        for (int mi = 0; mi < 4; ++mi)
#pragma unroll
            for (int hf = 0; hf < 2; ++hf) {
                const int m = bm0 + wm * 64 + mi * 16 + grp + hf * 8;
#pragma unroll
                for (int pr = 0; pr < 2; ++pr) {
                    float zi = acc[mi][pr][hf * 2]         + bg[jsl + pr * 8 + 2 * tig];
                    float zf = acc[mi][pr][hf * 2 + 1]     + bg[jsl + pr * 8 + 2 * tig + 1];
                    float zg = acc[mi][2 + pr][hf * 2]     + bg[jsl + 16 + pr * 8 + 2 * tig];
                    float zo = acc[mi][2 + pr][hf * 2 + 1] + bg[jsl + 16 + pr * 8 + 2 * tig + 1];
                    float ig = 1.f / (1.f + expf(-zi));
                    float fg = 1.f / (1.f + expf(-zf));
                    float gg = tanhf(zg);
                    float og = 1.f / (1.f + expf(-zo));
                    const int u = ubl + pr * 4 + tig;
                    const size_t ci = (size_t)m * U_ + u;
                    float cn = fmaf(fg, g_c[ci], ig * gg);
                    g_c[ci] = cn;
                    float hn = og * tanhf(cn);
                    __nv_bfloat16 hi = __float2bfloat16(hn);
                    hwh[ci] = hi;
                    hwl[ci] = __float2bfloat16(hn - __bfloat162float(hi));
                }
            }
    } else {
#pragma unroll
        for (int mi = 0; mi < 4; ++mi)
#pragma unroll
            for (int hf = 0; hf < 2; ++hf) {
                const int m = bm0 + wm * 64 + mi * 16 + grp + hf * 8;
                float* orow = outp + (size_t)m * (S_ * F_);
#pragma unroll
                for (int ni = 0; ni < 4; ++ni) {
                    const int f = wn * 32 + ni * 8 + 2 * tig;
                    orow[f]     = acc[mi][ni][hf * 2]     + bd[f];
                    orow[f + 1] = acc[mi][ni][hf * 2 + 1] + bd[f + 1];
                }
            }
    }
}

// ---------------- host launch ----------------------------------------------
extern "C" void kernel_launch(void* const* d_in, const int* in_sizes, int n_in,
                              void* d_out, int out_size) {
    const float* inputs = (const float*)d_in[0];
    const float* Wk     = (const float*)d_in[1];
    const float* Wr     = (const float*)d_in[2];
    const float* b      = (const float*)d_in[3];
    const float* Wd     = (const float*)d_in[4];
    const float* bd     = (const float*)d_in[5];
    float* out = (float*)d_out;

    // ---- setup (every call; deterministic) ----
    k_split_x<<<(B_ * T_ * F_) / 256, 256>>>(inputs);
    k_init_state<<<(B_ * U_ + 255) / 256, 256>>>();
    k_build_warm<<<(int)(((size_t)NG * KPW + 255) / 256), 256>>>(Wk, Wr, b);
    k_dec_weight<<<dim3(KD, 2), 256>>>(Wk, Wr, Wd);
    k_build_dec<<<(int)(((size_t)NDEC * KPD + 255) / 256), 256>>>(Wd);
    k_bias_dec<<<NG / 256, 256>>>(Wk, b, bd);

    int q = 0;
    // warmup: 128 steps, 16 cell N-tiles x 8 M-tiles
    for (int t = 0; t < T_; ++t, ++q) {
        k_step<<<dim3(16, 8), 256>>>(
            /*warm=*/1, /*xoff=*/t * F_, /*hrIdx=*/q & 1,
            /*nCellTiles=*/16, /*bxOff=*/0, bd, out);
    }
    // decode s=1..95: 16 cell tiles + 1 pred tile (writes out[:, s-1, :])
    for (int s = 1; s < S_; ++s, ++q) {
        k_step<<<dim3(17, 8), 256>>>(
            /*warm=*/0, /*xoff=*/0, /*hrIdx=*/q & 1,
            /*nCellTiles=*/16, /*bxOff=*/0, bd, out + (size_t)(s - 1) * F_);
    }
    // final pred-only: out[:, S-1, :] from the last h
    k_step<<<dim3(1, 8), 256>>>(
        /*warm=*/0, /*xoff=*/0, /*hrIdx=*/q & 1,
        /*nCellTiles=*/0, /*bxOff=*/16, bd, out + (size_t)(S_ - 1) * F_);
}

// round 4
// speedup vs baseline: 2.8363x; 1.8367x over previous
#include <cuda_runtime.h>
#include <cuda_bf16.h>
#include <cstdint>

// Problem constants (fixed for FeedBack_953482740249)
#define B_   1024
#define T_   128
#define F_   128
#define U_   512
#define S_   96
#define NG   2048
#define KD   512

#define TILEB    8192            // one 128x32 bf16 tile (64B rows, swizzled)
#define STAGEB   32768           // Ah,Al,Bh,Bl
#define NSTAGE   4
#define SMEM_DYN (NSTAGE * STAGEB)

// ---------------- device globals (no allocations allowed) ------------------
__device__ __align__(128) unsigned char g_xP[(size_t)8 * 128 * 4 * 16384];  // 64MB packed x (hi+lo)
__device__ __align__(128) unsigned char g_WwP[(size_t)16 * 20 * 16384];     // warm weights packed
__device__ __align__(128) unsigned char g_WdP[(size_t)17 * 16 * 16384];     // dec weights (+ Wd^T tile)
__device__ __align__(128) unsigned char g_hP[2][(size_t)8 * 16 * 16384];    // ping-pong packed h
__device__ __align__(128) float g_Wdec[(size_t)KD * NG];                    // fp32 temp Wr + Wd@Wk
__device__ float g_bwarm[NG];
__device__ float g_bdec[NG];
__device__ float g_c[B_ * U_];

// Column permutation: permuted col j -> original col gate*U + unit
__device__ __forceinline__ int perm_col(int j) {
    int gate = ((j >> 4) & 1) * 2 + (j & 1);
    int unit = (j >> 5) * 8 + ((j >> 1) & 7);
    return gate * U_ + unit;
}
// Byte offset inside one 128x32 tile: 64B rows, 16B-seg XOR swizzle
__device__ __forceinline__ int toff(int row, int col) {
    return row * 64 + ((((col >> 3) ^ ((row >> 1) & 3)) << 4)) + ((col & 7) << 1);
}

// ---------------- PTX helpers ----------------------------------------------
__device__ __forceinline__ uint32_t smem_u32(const void* p) {
    uint32_t a;
    asm("{ .reg .u64 t; cvta.to.shared.u64 t, %1; cvt.u32.u64 %0, t; }"
        : "=r"(a) : "l"(p));
    return a;
}
__device__ __forceinline__ void mbar_init(uint32_t a, uint32_t cnt) {
    asm volatile("mbarrier.init.shared.b64 [%0], %1;" :: "r"(a), "r"(cnt) : "memory");
}
__device__ __forceinline__ void mbar_expect_tx(uint32_t a, uint32_t bytes) {
    asm volatile("mbarrier.arrive.expect_tx.shared.b64 _, [%0], %1;"
                 :: "r"(a), "r"(bytes) : "memory");
}
__device__ __forceinline__ void mbar_wait(uint32_t a, uint32_t parity) {
    asm volatile(
        "{\n\t.reg .pred P;\n\t"
        "WL_%=:\n\t"
        "mbarrier.try_wait.parity.acquire.cta.shared::cta.b64 P, [%0], %1, 0x989680;\n\t"
        "@P bra WD_%=;\n\t"
        "bra WL_%=;\n\t"
        "WD_%=:\n\t}"
        :: "r"(a), "r"(parity) : "memory");
}
__device__ __forceinline__ void fence_async() {
    asm volatile("fence.proxy.async.shared::cta;" ::: "memory");
}
// 1D bulk copy global -> shared, mbarrier completion (sm_90 baseline feature)
__device__ __forceinline__ void bulk_g2s(uint32_t dst, const void* gsrc,
                                         uint32_t bytes, uint32_t mbar) {
    asm volatile(
        "{\n\t.reg .u64 gs;\n\t"
        "cvta.to.global.u64 gs, %1;\n\t"
        "cp.async.bulk.shared::cluster.global.mbarrier::complete_tx::bytes [%0], [gs], %2, [%3];\n\t}"
        :: "r"(dst), "l"(gsrc), "r"(bytes), "r"(mbar) : "memory");
}
__device__ __forceinline__ void ldx4(uint32_t* r, uint32_t addr) {
    asm volatile("ldmatrix.sync.aligned.m8n8.x4.shared.b16 {%0,%1,%2,%3}, [%4];"
        : "=r"(r[0]), "=r"(r[1]), "=r"(r[2]), "=r"(r[3]) : "r"(addr));
}
__device__ __forceinline__ void mma16816(float* d, const uint32_t* a, const uint32_t* b) {
    asm volatile(
        "mma.sync.aligned.m16n8k16.row.col.f32.bf16.bf16.f32 "
        "{%0,%1,%2,%3}, {%4,%5,%6,%7}, {%8,%9}, {%0,%1,%2,%3};"
        : "+f"(d[0]), "+f"(d[1]), "+f"(d[2]), "+f"(d[3])
        : "r"(a[0]), "r"(a[1]), "r"(a[2]), "r"(a[3]), "r"(b[0]), "r"(b[1]));
}

// ---------------- setup kernels --------------------------------------------
// Pack inputs x into per-(m_tile,t,k_chunk) swizzled hi/lo tiles.
__global__ void k_pack_x(const float* __restrict__ x) {
    int i = blockIdx.x * blockDim.x + threadIdx.x;   // m*T*F + t*F + f
    int f = i & 127;
    int t = (i >> 7) & 127;
    int m = i >> 14;
    float v = x[i];
    __nv_bfloat16 hi = __float2bfloat16(v);
    __nv_bfloat16 lo = __float2bfloat16(v - __bfloat162float(hi));
    int mt = m >> 7, rw = m & 127, kc = f >> 5, col = f & 31;
    size_t base = ((size_t)((mt * 128 + t) * 4 + kc)) * 16384 + toff(rw, col);
    *(__nv_bfloat16*)(g_xP + base)        = hi;
    *(__nv_bfloat16*)(g_xP + base + TILEB) = lo;
}

__global__ void k_init_state() {
    int i = blockIdx.x * blockDim.x + threadIdx.x;   // < 524288
    ((uint32_t*)g_hP[0])[i] = 0u;                    // 2MB zeros
    g_c[i] = 0.f;
}

// Warm weights: chunk k' covers k = chunk*32..; k<F from Wk else Wr. Permuted cols.
__global__ void k_pack_warm(const float* __restrict__ Wk,
                            const float* __restrict__ Wr,
                            const float* __restrict__ b) {
    int i = blockIdx.x * 256 + threadIdx.x;          // 16*20*128*32
    int col = i & 31;
    int rw  = (i >> 5) & 127;
    int ch  = (i >> 12) % 20;
    int nt  = i / (20 << 12);
    int j = nt * 128 + rw;
    int pc = perm_col(j);
    int k = ch * 32 + col;
    float v = (k < F_) ? Wk[(size_t)k * NG + pc] : Wr[(size_t)(k - F_) * NG + pc];
    __nv_bfloat16 hi = __float2bfloat16(v);
    __nv_bfloat16 lo = __float2bfloat16(v - __bfloat162float(hi));
    size_t base = ((size_t)(nt * 20 + ch)) * 16384 + toff(rw, col);
    *(__nv_bfloat16*)(g_WwP + base)        = hi;
    *(__nv_bfloat16*)(g_WwP + base + TILEB) = lo;
    if (ch == 0 && col == 0) g_bwarm[j] = b[pc];
}

// g_Wdec[k][col] = Wr[k][col] + sum_f Wd[k][f] * Wk[f][col]  (native cols)
__global__ void k_dec_weight(const float* __restrict__ Wk,
                             const float* __restrict__ Wr,
                             const float* __restrict__ Wd) {
    int k = blockIdx.x;
    int grp = blockIdx.y * 256 + threadIdx.x;
    int col0 = grp * 4;
    __shared__ float wd[F_];
    if (threadIdx.x < F_) wd[threadIdx.x] = Wd[k * F_ + threadIdx.x];
    __syncthreads();
    float4 acc = make_float4(0.f, 0.f, 0.f, 0.f);
    for (int f = 0; f < F_; ++f) {
        float4 wk = *(const float4*)&Wk[(size_t)f * NG + col0];
        float d = wd[f];
        acc.x = fmaf(d, wk.x, acc.x);
        acc.y = fmaf(d, wk.y, acc.y);
        acc.z = fmaf(d, wk.z, acc.z);
        acc.w = fmaf(d, wk.w, acc.w);
    }
    const float4 wr = *(const float4*)&Wr[(size_t)k * NG + col0];
    float4 o;
    o.x = acc.x + wr.x; o.y = acc.y + wr.y;
    o.z = acc.z + wr.z; o.w = acc.w + wr.w;
    *(float4*)&g_Wdec[(size_t)k * NG + col0] = o;
}

// Decode packed weights; n_tile 16 = Wd^T (natural col order).
__global__ void k_pack_dec(const float* __restrict__ Wd) {
    int i = blockIdx.x * 256 + threadIdx.x;          // 17*16*128*32
    int col = i & 31;
    int rw  = (i >> 5) & 127;
    int ch  = (i >> 12) & 15;
    int nt  = i >> 16;
    int j = nt * 128 + rw;
    int k = ch * 32 + col;
    float v = (j < NG) ? g_Wdec[(size_t)k * NG + perm_col(j)]
                       : Wd[(size_t)k * F_ + (j - NG)];
    __nv_bfloat16 hi = __float2bfloat16(v);
    __nv_bfloat16 lo = __float2bfloat16(v - __bfloat162float(hi));
    size_t base = ((size_t)(nt * 16 + ch)) * 16384 + toff(rw, col);
    *(__nv_bfloat16*)(g_WdP + base)        = hi;
    *(__nv_bfloat16*)(g_WdP + base + TILEB) = lo;
}

// g_bdec[j] = b[col] + sum_f bd[f]*Wk[f][col]   (permuted)
__global__ void k_bias_dec(const float* __restrict__ Wk,
                           const float* __restrict__ b,
                           const float* __restrict__ bd) {
    int j = blockIdx.x * blockDim.x + threadIdx.x;
    int col = perm_col(j);
    float acc = b[col];
    for (int f = 0; f < F_; ++f) acc = fmaf(bd[f], Wk[(size_t)f * NG + col], acc);
    g_bdec[j] = acc;
}

// ---------------- per-step kernel: bulk-fed mma.sync + fused LSTM ----------
__global__ __launch_bounds__(256, 1)
void k_step(int warm, int t, int hrIdx, int nCellTiles, int bxOff,
            const float* __restrict__ bd, float* __restrict__ outp)
{
    extern __shared__ __align__(128) unsigned char dsm[];
    __shared__ __align__(8) uint64_t mbarS[NSTAGE];

    const int tid  = threadIdx.x;
    const int lane = tid & 31;
    const int wid  = tid >> 5;
    const int wm   = wid & 1;     // 64 M-rows each
    const int wn   = wid >> 1;    // 32 N-cols each
    const int grp  = lane >> 2;
    const int tig  = lane & 3;

    const int bx  = blockIdx.x + bxOff;
    const int mt  = blockIdx.y;
    const int bm0 = mt * 128;
    const int bn0 = bx * 128;
    const bool isPred = (bx >= nCellTiles);

    const int nst = warm ? 20 : 16;
    const unsigned char* WP = warm ? g_WwP : g_WdP;
    const int wstride = warm ? 20 : 16;
    const unsigned char* hR = g_hP[hrIdx];

    const uint32_t sbase = smem_u32(dsm);
    const uint32_t mb = smem_u32(mbarS);

    if (tid == 0) {
        for (int i = 0; i < NSTAGE; ++i) mbar_init(mb + 8 * i, 1);
        fence_async();
    }
    __syncthreads();

    auto issue = [&](int s) {
        const uint32_t bar = mb + 8 * (s & 3);
        mbar_expect_tx(bar, STAGEB);
        const uint32_t d = sbase + (uint32_t)(s & 3) * STAGEB;
        const unsigned char* aP;
        if (warm && s < 4) aP = g_xP + ((size_t)((mt * 128 + t) * 4 + s)) * 16384;
        else               aP = hR + ((size_t)(mt * 16 + (warm ? s - 4 : s))) * 16384;
        const unsigned char* bP = WP + ((size_t)(bx * wstride + s)) * 16384;
        bulk_g2s(d,          aP, 16384, bar);
        bulk_g2s(d + 16384,  bP, 16384, bar);
    };
    if (tid == 0) {
        for (int s = 0; s < NSTAGE; ++s) issue(s);
    }

    float acc[4][4][4];
#pragma unroll
    for (int mi = 0; mi < 4; ++mi)
#pragma unroll
        for (int ni = 0; ni < 4; ++ni)
#pragma unroll
            for (int r = 0; r < 4; ++r) acc[mi][ni][r] = 0.f;

    // addressing invariants
    const int rowA0 = wm * 64 + (lane & 15);
    const int xrA   = (rowA0 >> 1) & 3;
    const int rowB0 = wn * 32 + (lane & 7) + ((lane >> 4) & 1) * 8;
    const int xrB   = (rowB0 >> 1) & 3;

    for (int s = 0; s < nst; ++s) {
        const int buf = s & 3;
        mbar_wait(mb + 8 * buf, (s >> 2) & 1);
        const uint32_t sA = sbase + (uint32_t)buf * STAGEB;

#pragma unroll
        for (int ks = 0; ks < 2; ++ks) {
            const int segA = ks * 2 + (lane >> 4);
            const uint32_t offA = (uint32_t)rowA0 * 64 + (uint32_t)((segA ^ xrA) << 4);
            const int segB = ks * 2 + ((lane >> 3) & 1);
            const uint32_t offB = (uint32_t)rowB0 * 64 + (uint32_t)((segB ^ xrB) << 4);

            uint32_t ah[4][4], al[4][4], bh[2][4], bl[2][4];
#pragma unroll
            for (int mi = 0; mi < 4; ++mi) ldx4(ah[mi], sA + offA + mi * 1024);
#pragma unroll
            for (int mi = 0; mi < 4; ++mi) ldx4(al[mi], sA + TILEB + offA + mi * 1024);
#pragma unroll
            for (int g = 0; g < 2; ++g) ldx4(bh[g], sA + 2 * TILEB + offB + g * 1024);
#pragma unroll
            for (int g = 0; g < 2; ++g) ldx4(bl[g], sA + 3 * TILEB + offB + g * 1024);

#pragma unroll
            for (int mi = 0; mi < 4; ++mi)
#pragma unroll
                for (int ni = 0; ni < 4; ++ni)
                    mma16816(acc[mi][ni], ah[mi], &bh[ni >> 1][(ni & 1) * 2]);
#pragma unroll
            for (int mi = 0; mi < 4; ++mi)
#pragma unroll
                for (int ni = 0; ni < 4; ++ni)
                    mma16816(acc[mi][ni], ah[mi], &bl[ni >> 1][(ni & 1) * 2]);
#pragma unroll
            for (int mi = 0; mi < 4; ++mi)
#pragma unroll
                for (int ni = 0; ni < 4; ++ni)
                    mma16816(acc[mi][ni], al[mi], &bh[ni >> 1][(ni & 1) * 2]);
        }
        __syncthreads();
        if (tid == 0 && s + NSTAGE < nst) {
            fence_async();
            issue(s + NSTAGE);
        }
    }

    // ---------------- fused epilogue ----------------
    if (!isPred) {
        const float* bg = warm ? g_bwarm : g_bdec;
        unsigned char* hW = g_hP[hrIdx ^ 1];
        const int jsl = bn0 + wn * 32;
        const uint32_t hbase = (uint32_t)((mt * 16 + bx) * 2) * TILEB;  // chunk == bx
#pragma unroll
        for (int mi = 0; mi < 4; ++mi)
#pragma unroll
            for (int hf = 0; hf < 2; ++hf) {
                const int rw = wm * 64 + mi * 16 + grp + hf * 8;
                const int m  = bm0 + rw;
                const uint32_t ho = hbase + (uint32_t)rw * 64
                                  + (uint32_t)((wn ^ ((rw >> 1) & 3)) << 4);
#pragma unroll
                for (int pr = 0; pr < 2; ++pr) {
                    float zi = acc[mi][pr][hf * 2]         + bg[jsl + pr * 8 + 2 * tig];
                    float zf = acc[mi][pr][hf * 2 + 1]     + bg[jsl + pr * 8 + 2 * tig + 1];
                    float zg = acc[mi][2 + pr][hf * 2]     + bg[jsl + 16 + pr * 8 + 2 * tig];
                    float zo = acc[mi][2 + pr][hf * 2 + 1] + bg[jsl + 16 + pr * 8 + 2 * tig + 1];
                    float ig = 1.f / (1.f + expf(-zi));
                    float fg = 1.f / (1.f + expf(-zf));
                    float gg = tanhf(zg);
                    float og = 1.f / (1.f + expf(-zo));
                    const int u = bx * 32 + wn * 8 + pr * 4 + tig;
                    const size_t ci = (size_t)m * U_ + u;
                    float cn = fmaf(fg, g_c[ci], ig * gg);
                    g_c[ci] = cn;
                    float hn = og * tanhf(cn);
                    __nv_bfloat16 hi = __float2bfloat16(hn);
                    __nv_bfloat16 lo = __float2bfloat16(hn - __bfloat162float(hi));
                    const int ce = (pr * 4 + tig) * 2;
                    *(__nv_bfloat16*)(hW + ho + ce)         = hi;
                    *(__nv_bfloat16*)(hW + TILEB + ho + ce) = lo;
                }
            }
    } else {
#pragma unroll
        for (int mi = 0; mi < 4; ++mi)
#pragma unroll
            for (int hf = 0; hf < 2; ++hf) {
                const int m = bm0 + wm * 64 + mi * 16 + grp + hf * 8;
                float* orow = outp + (size_t)m * (S_ * F_);
#pragma unroll
                for (int ni = 0; ni < 4; ++ni) {
                    const int f = wn * 32 + ni * 8 + 2 * tig;
                    orow[f]     = acc[mi][ni][hf * 2]     + bd[f];
                    orow[f + 1] = acc[mi][ni][hf * 2 + 1] + bd[f + 1];
                }
            }
    }
}

// ---------------- host launch ----------------------------------------------
extern "C" void kernel_launch(void* const* d_in, const int* in_sizes, int n_in,
                              void* d_out, int out_size) {
    const float* inputs = (const float*)d_in[0];
    const float* Wk     = (const float*)d_in[1];
    const float* Wr     = (const float*)d_in[2];
    const float* b      = (const float*)d_in[3];
    const float* Wd     = (const float*)d_in[4];
    const float* bd     = (const float*)d_in[5];
    float* out = (float*)d_out;

    cudaFuncSetAttribute(k_step, cudaFuncAttributeMaxDynamicSharedMemorySize, SMEM_DYN);

    // ---- setup (every call; deterministic) ----
    k_pack_x<<<(B_ * T_ * F_) / 256, 256>>>(inputs);
    k_init_state<<<(B_ * U_) / 256, 256>>>();
    k_pack_warm<<<(16 * 20 * 128 * 32) / 256, 256>>>(Wk, Wr, b);
    k_dec_weight<<<dim3(KD, 2), 256>>>(Wk, Wr, Wd);
    k_pack_dec<<<(17 * 16 * 128 * 32) / 256, 256>>>(Wd);
    k_bias_dec<<<NG / 256, 256>>>(Wk, b, bd);

    int q = 0;
    // warmup: 128 steps, 16 cell N-tiles x 8 M-tiles
    for (int t = 0; t < T_; ++t, ++q) {
        k_step<<<dim3(16, 8), 256, SMEM_DYN>>>(
            /*warm=*/1, /*t=*/t, /*hrIdx=*/q & 1,
            /*nCellTiles=*/16, /*bxOff=*/0, bd, out);
    }
    // decode s=1..95: 16 cell tiles + 1 pred tile (writes out[:, s-1, :])
    for (int s = 1; s < S_; ++s, ++q) {
        k_step<<<dim3(17, 8), 256, SMEM_DYN>>>(
            /*warm=*/0, /*t=*/0, /*hrIdx=*/q & 1,
            /*nCellTiles=*/16, /*bxOff=*/0, bd, out + (size_t)(s - 1) * F_);
    }
    // final pred-only: out[:, S-1, :] from the last h
    k_step<<<dim3(1, 8), 256, SMEM_DYN>>>(
        /*warm=*/0, /*t=*/0, /*hrIdx=*/q & 1,
        /*nCellTiles=*/0, /*bxOff=*/16, bd, out + (size_t)(S_ - 1) * F_);
}